// round 1
// baseline (speedup 1.0000x reference)
#include <cuda_runtime.h>
#include <math.h>

#define NN 50000
#define EE 400000
#define FF 128
#define F3 384
#define NRBF 20

// ---------------- scratch (__device__ globals; no allocation allowed) ----------------
__device__ float g_phi[NN * F3];     // 76.8 MB
__device__ float g_h[NN * FF];       // 25.6 MB
__device__ float g_rbf[NRBF * EE];   // 32   MB  (SoA: [k][pos], CSR order)
__device__ float g_dirn[3 * EE];     // 4.8  MB  (SoA, CSR order)
__device__ int   g_cnt[NN];
__device__ int   g_off[NN + 1];
__device__ int   g_cur[NN];
__device__ int   g_order[EE];

// ---------------- CSR build ----------------
__global__ void k_zero() {
    int i = blockIdx.x * blockDim.x + threadIdx.x;
    if (i < NN) g_cnt[i] = 0;
}

__global__ void k_hist(const float* __restrict__ r) {
    int e = blockIdx.x * blockDim.x + threadIdx.x;
    if (e < EE) {
        int j = (int)r[e * 5 + 1];
        atomicAdd(&g_cnt[j], 1);
    }
}

__global__ void k_scan() {
    __shared__ int part[1024];
    int t = threadIdx.x;
    const int CH = (NN + 1023) / 1024;   // 49
    int base = t * CH, sum = 0;
    for (int i = 0; i < CH; i++) {
        int idx = base + i;
        if (idx < NN) sum += g_cnt[idx];
    }
    part[t] = sum;
    __syncthreads();
    for (int off = 1; off < 1024; off <<= 1) {
        int v = (t >= off) ? part[t - off] : 0;
        __syncthreads();
        part[t] += v;
        __syncthreads();
    }
    int run = (t > 0) ? part[t - 1] : 0;
    for (int i = 0; i < CH; i++) {
        int idx = base + i;
        if (idx < NN) {
            g_off[idx] = run;
            g_cur[idx] = run;
            run += g_cnt[idx];
        }
    }
    if (t == 1023) g_off[NN] = part[1023];
}

__global__ void k_fill(const float* __restrict__ r) {
    int e = blockIdx.x * blockDim.x + threadIdx.x;
    if (e < EE) {
        int j = (int)r[e * 5 + 1];
        int pos = atomicAdd(&g_cur[j], 1);
        g_order[pos] = e;
    }
}

// deterministic per-node edge order (atomic fill order varies per replay)
__global__ void k_sortlists() {
    int n = blockIdx.x * blockDim.x + threadIdx.x;
    if (n >= NN) return;
    int s0 = g_off[n], s1 = g_off[n + 1];
    for (int i = s0 + 1; i < s1; i++) {
        int key = g_order[i];
        int j = i - 1;
        while (j >= s0 && g_order[j] > key) {
            g_order[j + 1] = g_order[j];
            j--;
        }
        g_order[j + 1] = key;
    }
}

// ---------------- per-edge precompute: rbf[20] and dirn[3], written in CSR order ----------------
__global__ void k_edge(const float* __restrict__ r) {
    int p = blockIdx.x * blockDim.x + threadIdx.x;
    if (p >= EE) return;
    int eid = g_order[p];
    float rx = r[eid * 5 + 2];
    float ry = r[eid * 5 + 3];
    float rz = r[eid * 5 + 4];
    float z = fabsf(rz);
    float inv = 1.0f / (z + 1e-8f);
#pragma unroll
    for (int k = 0; k < NRBF; k++) {
        float nk = (float)(k + 1) * 0.6283185307179586f;   // n * pi/5
        g_rbf[k * EE + p] = sinf(nk * z) * inv;
    }
    float nrm = sqrtf(rx * rx + ry * ry + rz * rz);
    float invn = 1.0f / (nrm + 1e-8f);
    g_dirn[p]           = rx * invn;
    g_dirn[EE + p]      = ry * invn;
    g_dirn[2 * EE + p]  = rz * invn;
}

// ---------------- fp32 GEMM: C = act(A@B + bias), A:MxK, B:KxN row-major ----------------
// BM=128 BN=64 BK=16, 256 threads, 8x4 microtile
template <bool SILU>
__global__ void __launch_bounds__(256) k_gemm(const float* __restrict__ A,
                                              const float* __restrict__ B,
                                              const float* __restrict__ bias,
                                              float* __restrict__ C,
                                              int M, int N, int K) {
    __shared__ float As[16][132];   // transposed A tile, padded
    __shared__ float Bs[16][64];
    int t = threadIdx.x;
    int rowBase = blockIdx.y * 128;
    int colBase = blockIdx.x * 64;
    int tm = (t >> 4) << 3;   // 0..120 step 8
    int tn = (t & 15) << 2;   // 0..60  step 4
    float acc[8][4];
#pragma unroll
    for (int i = 0; i < 8; i++) {
#pragma unroll
        for (int j = 0; j < 4; j++) acc[i][j] = 0.f;
    }
    int ar = t >> 2;          // 0..63
    int ak = (t & 3) << 2;    // 0,4,8,12
    int brow = t >> 4;        // 0..15
    int bcol = (t & 15) << 2; // 0..60

    for (int kt = 0; kt < K; kt += 16) {
#pragma unroll
        for (int h = 0; h < 2; h++) {
            int row = ar + h * 64;
            int grow = rowBase + row;
            float4 a4 = make_float4(0.f, 0.f, 0.f, 0.f);
            if (grow < M) a4 = *(const float4*)&A[grow * K + kt + ak];
            As[ak + 0][row] = a4.x;
            As[ak + 1][row] = a4.y;
            As[ak + 2][row] = a4.z;
            As[ak + 3][row] = a4.w;
        }
        *(float4*)&Bs[brow][bcol] = *(const float4*)&B[(kt + brow) * N + colBase + bcol];
        __syncthreads();
#pragma unroll
        for (int k = 0; k < 16; k++) {
            float4 a0 = *(float4*)&As[k][tm];
            float4 a1v = *(float4*)&As[k][tm + 4];
            float4 b0 = *(float4*)&Bs[k][tn];
            float a[8] = {a0.x, a0.y, a0.z, a0.w, a1v.x, a1v.y, a1v.z, a1v.w};
            float b[4] = {b0.x, b0.y, b0.z, b0.w};
#pragma unroll
            for (int i = 0; i < 8; i++) {
#pragma unroll
                for (int j = 0; j < 4; j++) acc[i][j] = fmaf(a[i], b[j], acc[i][j]);
            }
        }
        __syncthreads();
    }
#pragma unroll
    for (int i = 0; i < 8; i++) {
        int grow = rowBase + tm + i;
        if (grow < M) {
            float4 o;
            float bv[4];
#pragma unroll
            for (int j = 0; j < 4; j++) {
                float val = acc[i][j] + bias[colBase + tn + j];
                if (SILU) val = val / (1.0f + __expf(-val));
                bv[j] = val;
            }
            o.x = bv[0]; o.y = bv[1]; o.z = bv[2]; o.w = bv[3];
            *(float4*)&C[grow * N + colBase + tn] = o;
        }
    }
}

// ---------------- cutoff: 0.5*(cos(pi*x/5)+1)*(x<5), MUFU-free ----------------
// cos(pi*x/5) = cos(2*pi*u), u = x/10 reduced to [-0.5,0.5]; even series in u^2, |err| <~ 4e-6
__device__ __forceinline__ float cutW(float x) {
    float u = x * 0.1f;
    u = u - rintf(u);
    float w = u * u;
    float c = -1.714374f;
    c = fmaf(c, w, 7.903536f);
    c = fmaf(c, w, -26.425825f);
    c = fmaf(c, w, 60.244630f);
    c = fmaf(c, w, -85.456806f);
    c = fmaf(c, w, 64.939394f);
    c = fmaf(c, w, -19.739209f);
    c = fmaf(c, w, 1.0f);
    float Wv = fmaf(0.5f, c, 0.5f);
    return (x < 5.0f) ? Wv : 0.0f;
}

// ---------------- main per-node kernel: no atomics, register accumulation ----------------
__global__ void __launch_bounds__(128) k_main(const float* __restrict__ v,
                                              const float* __restrict__ Wr,
                                              const float* __restrict__ br,
                                              float* __restrict__ out) {
    int tid = threadIdx.x;   // feature f = tid (0..127)
    // Wr columns tid, tid+128, tid+256 resident in registers (60 floats)
    float wr0[NRBF], wr1[NRBF], wr2[NRBF];
#pragma unroll
    for (int k = 0; k < NRBF; k++) {
        wr0[k] = Wr[k * F3 + tid];
        wr1[k] = Wr[k * F3 + FF + tid];
        wr2[k] = Wr[k * F3 + 2 * FF + tid];
    }
    float br0 = br[tid], br1 = br[FF + tid], br2 = br[2 * FF + tid];

    for (int n = blockIdx.x; n < NN; n += gridDim.x) {
        int p0 = g_off[n], p1e = g_off[n + 1];
        float a1 = 0.f, a2 = 0.f, bx = 0.f, by = 0.f, bz = 0.f;
        for (int p = p0; p < p1e; p++) {
            float x0 = br0, x1 = br1, x2 = br2;
#pragma unroll
            for (int k = 0; k < NRBF; k++) {
                float rb = __ldg(&g_rbf[k * EE + p]);   // broadcast across block
                x0 = fmaf(rb, wr0[k], x0);
                x1 = fmaf(rb, wr1[k], x1);
                x2 = fmaf(rb, wr2[k], x2);
            }
            float W0 = cutW(x0);
            float W1v = cutW(x1);
            float W2v = cutW(x2);
            float dx = __ldg(&g_dirn[p]);
            float dy = __ldg(&g_dirn[EE + p]);
            float dz = __ldg(&g_dirn[2 * EE + p]);
            a1 += W0;
            a2 += W1v;
            bx = fmaf(W2v, dx, bx);
            by = fmaf(W2v, dy, by);
            bz = fmaf(W2v, dz, bz);
        }
        float ph1 = g_phi[n * F3 + tid];
        float ph2 = g_phi[n * F3 + FF + tid];
        float ph3 = g_phi[n * F3 + 2 * FF + tid];
        int nf = n * FF + tid;
        float vx = v[nf * 3 + 0], vy = v[nf * 3 + 1], vz = v[nf * 3 + 2];
        float s1v = ph1 * a1;
        out[nf * 3 + 0] = fmaf(vx, s1v, ph3 * bx);
        out[nf * 3 + 1] = fmaf(vy, s1v, ph3 * by);
        out[nf * 3 + 2] = fmaf(vz, s1v, ph3 * bz);
        out[NN * F3 + nf] = ph2 * a2;   // delta_s
    }
}

// ---------------- launch ----------------
extern "C" void kernel_launch(void* const* d_in, const int* in_sizes, int n_in,
                              void* d_out, int out_size) {
    (void)in_sizes; (void)n_in; (void)out_size;
    const float* v  = (const float*)d_in[0];
    const float* s  = (const float*)d_in[1];
    const float* r  = (const float*)d_in[2];
    const float* W1 = (const float*)d_in[3];
    const float* b1 = (const float*)d_in[4];
    const float* W2 = (const float*)d_in[5];
    const float* b2 = (const float*)d_in[6];
    const float* Wr = (const float*)d_in[7];
    const float* br = (const float*)d_in[8];
    float* out = (float*)d_out;

    void* q;
    cudaGetSymbolAddress(&q, g_h);
    float* hptr = (float*)q;
    cudaGetSymbolAddress(&q, g_phi);
    float* pptr = (float*)q;

    // CSR build
    k_zero<<<(NN + 255) / 256, 256>>>();
    k_hist<<<(EE + 255) / 256, 256>>>(r);
    k_scan<<<1, 1024>>>();
    k_fill<<<(EE + 255) / 256, 256>>>(r);
    k_sortlists<<<(NN + 127) / 128, 128>>>();
    // per-edge precompute (CSR order)
    k_edge<<<(EE + 127) / 128, 128>>>(r);
    // phi = silu(s@W1+b1)@W2+b2
    {
        dim3 g1(FF / 64, (NN + 127) / 128);
        k_gemm<true><<<g1, 256>>>(s, W1, b1, hptr, NN, FF, FF);
        dim3 g2(F3 / 64, (NN + 127) / 128);
        k_gemm<false><<<g2, 256>>>(hptr, W2, b2, pptr, NN, F3, FF);
    }
    // per-node fused edge GEMM + cutoff + accumulate + outputs
    k_main<<<2048, 128>>>(v, Wr, br, out);
}